// round 16
// baseline (speedup 1.0000x reference)
#include <cuda_runtime.h>
#include <cuda_fp16.h>
#include <math.h>
#include <stdint.h>

// Problem constants
#define S 2048
#define HID 2048
#define NH 16
#define NKV 4
#define HD 128
#define GRP (NH / NKV)
#define EPS 1e-6f
#define NQKV 3072  // NH*HD + 2*NKV*HD

// ---------------------------------------------------------------------------
// Scratch (device globals; allocation is forbidden)
// ---------------------------------------------------------------------------
__device__ float g_qkv[S * NQKV];          // fused QKV proj out (fp32)
__device__ half  g_x16[S * HID];           // X fp16 (natural [S][HID])
__device__ half  g_wqkv16[HID * NQKV];     // fused W fp16, natural [K][N]
__device__ half  g_wo16[HID * HID];        // Wo fp16, natural [K][N]
__device__ half  g_q16[NH * S * HD];       // Q fp16 (pre-scaled, log2 domain)
__device__ half  g_k16[NKV * S * HD];      // K fp16 [kv][s][d]
__device__ half  g_v16[NKV * S * HD];      // V fp16 [kv][s][d]
__device__ half  g_o16[S * HID];           // attention out fp16
__device__ float g_proj[S * HID];          // pre-final-norm

// ---------------------------------------------------------------------------
// PTX helpers (sm_80+ PTX only — legal under compute_103)
// ---------------------------------------------------------------------------
__device__ __forceinline__ uint32_t smem_u32(const void* p) {
    uint32_t a;
    asm("{ .reg .u64 t; cvta.to.shared.u64 t, %1; cvt.u32.u64 %0, t; }"
        : "=r"(a) : "l"(p));
    return a;
}

#define CP_ASYNC16(dst, src) \
    asm volatile("cp.async.cg.shared.global [%0], [%1], 16;" \
        :: "r"(dst), "l"(src))
#define CP_COMMIT() asm volatile("cp.async.commit_group;" ::: "memory")
#define CP_WAIT0() asm volatile("cp.async.wait_group 0;" ::: "memory")
#define CP_WAIT1() asm volatile("cp.async.wait_group 1;" ::: "memory")
#define CP_WAIT2() asm volatile("cp.async.wait_group 2;" ::: "memory")

#define LDSM_X4(r0, r1, r2, r3, addr) \
    asm volatile("ldmatrix.sync.aligned.m8n8.x4.shared.b16 {%0,%1,%2,%3}, [%4];" \
        : "=r"(r0), "=r"(r1), "=r"(r2), "=r"(r3) : "r"(addr))

#define LDSM_X4_TRANS(r0, r1, r2, r3, addr) \
    asm volatile("ldmatrix.sync.aligned.m8n8.x4.trans.shared.b16 {%0,%1,%2,%3}, [%4];" \
        : "=r"(r0), "=r"(r1), "=r"(r2), "=r"(r3) : "r"(addr))

#define MMA_FP16(d, a, b0, b1) \
    asm volatile("mma.sync.aligned.m16n8k16.row.col.f32.f16.f16.f32 " \
        "{%0,%1,%2,%3}, {%4,%5,%6,%7}, {%8,%9}, {%0,%1,%2,%3};" \
        : "+f"((d)[0]), "+f"((d)[1]), "+f"((d)[2]), "+f"((d)[3]) \
        : "r"((a)[0]), "r"((a)[1]), "r"((a)[2]), "r"((a)[3]), \
          "r"(b0), "r"(b1))

__device__ __forceinline__ uint32_t pack_f16(float v0, float v1) {
    half h0 = __float2half_rn(v0);
    half h1 = __float2half_rn(v1);
    return (uint32_t)__half_as_ushort(h0) |
           ((uint32_t)__half_as_ushort(h1) << 16);
}

// ---------------------------------------------------------------------------
// fp16 GEMM: C[M,N] = A16[M,K] @ B16[K,N]  (B natural row-major; fragments
// built with ldmatrix.trans). CTA tile 128x64, warp 32x32, BK=64, 3-stage
// cp.async, 24 KB/stage -> 72 KB smem, 2 CTAs/SM.
// ---------------------------------------------------------------------------
__global__ __launch_bounds__(256, 2) void mma_gemm_f16(
    int M, int N, int K,
    const half* __restrict__ A16, int lda,
    const half* __restrict__ B16, int ldb,
    float* __restrict__ C, int ldc)
{
    constexpr int BM = 128, BN = 64, BK = 64;
    constexpr int ASUB = BM * BK * 2;      // 16 KB
    constexpr int BSUB = BK * BN * 2;      // 8 KB
    constexpr int STAGE = ASUB + BSUB;     // 24 KB

    const int m0 = blockIdx.y * BM;
    const int n0 = blockIdx.x * BN;
    const int nIter = K / BK;

    extern __shared__ char smem[];
    const uint32_t sbase = smem_u32(smem);

    const int tid  = threadIdx.x;
    const int wid  = tid >> 5;
    const int lane = tid & 31;
    const int wm   = wid >> 1;
    const int wn   = wid & 1;

    auto load_stage = [&](int st, int k0) {
        const uint32_t base = sbase + st * STAGE;
#pragma unroll
        for (int t = 0; t < 4; t++) {
            int idx = tid + t * 256;          // A: 128 rows x 8 chunks
            int r = idx >> 3;
            int c = idx & 7;
            uint32_t soff = (uint32_t)(r * 128 + ((c ^ (r & 7)) << 4));
            long long ga = (long long)(m0 + r) * lda + k0 + c * 8;
            CP_ASYNC16(base + soff, (const char*)(A16 + ga));
        }
#pragma unroll
        for (int t = 0; t < 2; t++) {
            int idx = tid + t * 256;          // B: 64 k-rows x 8 n-chunks
            int r = idx >> 3;
            int c = idx & 7;
            uint32_t soff = (uint32_t)(r * 128 + ((c ^ (r & 7)) << 4));
            long long gb = (long long)(k0 + r) * ldb + n0 + c * 8;
            CP_ASYNC16(base + ASUB + soff, (const char*)(B16 + gb));
        }
        CP_COMMIT();
    };

    const int lrow = lane & 15;
    const int lsel = lane >> 4;
    int arow[2];
#pragma unroll
    for (int mt = 0; mt < 2; mt++) arow[mt] = wm * 32 + mt * 16 + lrow;

    float acc[2][4][4];
#pragma unroll
    for (int mt = 0; mt < 2; mt++)
#pragma unroll
        for (int j = 0; j < 4; j++)
#pragma unroll
            for (int e = 0; e < 4; e++) acc[mt][j][e] = 0.0f;

    load_stage(0, 0);
    if (nIter > 1) load_stage(1, BK);

    for (int it = 0; it < nIter; it++) {
        if (it + 2 < nIter) { load_stage((it + 2) % 3, (it + 2) * BK); CP_WAIT2(); }
        else if (it + 1 < nIter) { CP_WAIT1(); }
        else { CP_WAIT0(); }
        __syncthreads();

        const uint32_t base = sbase + (it % 3) * STAGE;
#pragma unroll
        for (int ks = 0; ks < 4; ks++) {
            const int achunk = ks * 2 + lsel;
            uint32_t ah[2][4], bt[2][4];
#pragma unroll
            for (int mt = 0; mt < 2; mt++) {
                uint32_t off = (uint32_t)(arow[mt] * 128 +
                               ((achunk ^ (arow[mt] & 7)) << 4));
                LDSM_X4(ah[mt][0], ah[mt][1], ah[mt][2], ah[mt][3], base + off);
            }
            int krow = ks * 16 + lrow;
#pragma unroll
            for (int g = 0; g < 2; g++) {
                int c = wn * 4 + g * 2 + lsel;
                uint32_t off = (uint32_t)(krow * 128 + ((c ^ (krow & 7)) << 4));
                LDSM_X4_TRANS(bt[g][0], bt[g][1], bt[g][2], bt[g][3],
                              base + ASUB + off);
            }
#pragma unroll
            for (int mt = 0; mt < 2; mt++)
#pragma unroll
                for (int j = 0; j < 4; j++) {
                    int g = j >> 1, o = j & 1;
                    MMA_FP16(acc[mt][j], ah[mt], bt[g][2 * o], bt[g][2 * o + 1]);
                }
        }
        __syncthreads();
    }

    const int er = lane >> 2;
    const int ec = (lane & 3) * 2;
#pragma unroll
    for (int mt = 0; mt < 2; mt++) {
        int r0 = m0 + wm * 32 + mt * 16 + er;
#pragma unroll
        for (int j = 0; j < 4; j++) {
            int col = n0 + wn * 32 + j * 8 + ec;
            *reinterpret_cast<float2*>(C + (long long)r0 * ldc + col) =
                make_float2(acc[mt][j][0], acc[mt][j][1]);
            *reinterpret_cast<float2*>(C + (long long)(r0 + 8) * ldc + col) =
                make_float2(acc[mt][j][2], acc[mt][j][3]);
        }
    }
}

// ---------------------------------------------------------------------------
// Fused flash attention: BQ=64, 4 warps, 128 threads, 2 CTAs/SM, 3-stage KV
// ring. SOFTWARE-PIPELINED: S for tile j+1 is computed before softmax(j) and
// PV(j), so the independent S-MMA chain overlaps the serial softmax chain.
// Ring safety: S_next reads slot (j+1)%3; iter-j prefetch writes (j+2)%3;
// slot j%3 is only overwritten by the iter-(j+1) prefetch, which follows the
// iter-(j+1) barrier (all PV(j) reads complete).
// ---------------------------------------------------------------------------
__global__ __launch_bounds__(128, 2) void flash_kernel(
    const half* __restrict__ q16, const half* __restrict__ k16,
    const half* __restrict__ v16, half* __restrict__ o16)
{
    constexpr int BQ = 64, BKV = 64;
    constexpr int QB = BQ * HD * 2;            // 16 KB
    constexpr int KVB = BKV * HD * 2;          // 16 KB each
    constexpr int STAGE = 2 * KVB;             // 32 KB (K + V)

    const int h   = blockIdx.y;
    const int qt  = gridDim.x - 1 - blockIdx.x;  // largest m0 first
    const int m0  = qt * BQ;
    const int kvh = h / GRP;
    const int jn  = qt + 1;

    const half* q_h = q16 + (long long)h * S * HD;
    const half* k_h = k16 + (long long)kvh * S * HD;
    const half* v_h = v16 + (long long)kvh * S * HD;

    extern __shared__ char smem[];
    const uint32_t sbase = smem_u32(smem);

    const int tid  = threadIdx.x;
    const int w    = tid >> 5;
    const int lane = tid & 31;
    const int lrow = lane & 15;
    const int lsel = lane >> 4;

    auto load_q = [&]() {
#pragma unroll
        for (int t = 0; t < 8; t++) {
            int idx = tid + t * 128;            // [0, 1024): 64 rows x 16 c
            int r = idx >> 4, c = idx & 15;
            uint32_t soff = (uint32_t)(r * 256 + ((c ^ (r & 7)) << 4));
            long long g = (long long)(m0 + r) * HD + c * 8;
            CP_ASYNC16(sbase + soff, (const char*)(q_h + g));
        }
    };
    auto load_stage = [&](int st, int kv0) {
        const uint32_t base = sbase + QB + st * STAGE;
#pragma unroll
        for (int t = 0; t < 8; t++) {           // K: 64 rows x 16 chunks
            int idx = tid + t * 128;
            int r = idx >> 4, c = idx & 15;
            uint32_t soff = (uint32_t)(r * 256 + ((c ^ (r & 7)) << 4));
            long long g = (long long)(kv0 + r) * HD + c * 8;
            CP_ASYNC16(base + soff, (const char*)(k_h + g));
        }
#pragma unroll
        for (int t = 0; t < 8; t++) {           // V: 64 rows x 16 chunks
            int idx = tid + t * 128;
            int r = idx >> 4, c = idx & 15;
            uint32_t soff = (uint32_t)(r * 256 + ((c ^ (r & 7)) << 4));
            long long g = (long long)(kv0 + r) * HD + c * 8;
            CP_ASYNC16(base + KVB + soff, (const char*)(v_h + g));
        }
        CP_COMMIT();
    };

    load_q();
    load_stage(0, 0);
    CP_COMMIT();                     // group: Q + stage0
    if (jn > 1) load_stage(1, BKV);  // group: stage1

    // Wait for Q + stage0 (pending: {g0} or {g0, g1}).
    if (jn > 1) CP_WAIT1(); else CP_WAIT0();
    __syncthreads();

    // Q fragments held in registers for the whole kernel
    uint32_t qh[8][4];
    {
        int row = w * 16 + lrow;
#pragma unroll
        for (int kchunk = 0; kchunk < 8; kchunk++) {
            int c = kchunk * 2 + lsel;
            uint32_t off = (uint32_t)(row * 256 + ((c ^ (row & 7)) << 4));
            LDSM_X4(qh[kchunk][0], qh[kchunk][1], qh[kchunk][2],
                    qh[kchunk][3], sbase + off);
        }
    }

    // S = Q K^T from a ring slot into dst
    auto compute_S = [&](float (*dst)[4], int slot) {
        const uint32_t base = sbase + QB + slot * STAGE;
#pragma unroll
        for (int nt = 0; nt < 8; nt++)
#pragma unroll
            for (int e = 0; e < 4; e++) dst[nt][e] = 0.0f;
#pragma unroll
        for (int kchunk = 0; kchunk < 8; kchunk++) {
            int c = kchunk * 2 + lsel;
#pragma unroll
            for (int g = 0; g < 4; g++) {
                int row = g * 16 + lrow;
                uint32_t off = (uint32_t)(row * 256 + ((c ^ (row & 7)) << 4));
                uint32_t bh[4];
                LDSM_X4(bh[0], bh[1], bh[2], bh[3], base + off);
#pragma unroll
                for (int o = 0; o < 2; o++)
                    MMA_FP16(dst[g * 2 + o], qh[kchunk], bh[o], bh[2 + o]);
            }
        }
    };

    float oacc[16][4];
#pragma unroll
    for (int nt = 0; nt < 16; nt++)
#pragma unroll
        for (int e = 0; e < 4; e++) oacc[nt][e] = 0.0f;
    float mrow[2] = {-1e30f, -1e30f};
    float lsum[2] = {0.0f, 0.0f};

    const int rg0 = m0 + w * 16 + (lane >> 2);
    const int cb  = (lane & 3) * 2;

    float scur[8][4];
    compute_S(scur, 0);   // S_0 (stage 0 resident)

    for (int j = 0; j < jn; j++) {
        const bool masked = (j == jn - 1);   // diagonal tile is always last

        __syncthreads();   // all warps done with iter j-1 (PV reads of slot (j-1)%3)
        if (j + 2 < jn) load_stage((j + 2) % 3, (j + 2) * BKV);

        float snext[8][4];
        const bool have_next = (j + 1 < jn);
        if (have_next) {
            // pending: {stage j+1} (+ {stage j+2} if just prefetched)
            if (j + 2 < jn) CP_WAIT1(); else CP_WAIT0();
            compute_S(snext, (j + 1) % 3);   // independent of softmax below
        }

        // ---- causal mask (diagonal tile only) ----
        if (masked) {
            const int kv0 = j * BKV;
#pragma unroll
            for (int nt = 0; nt < 8; nt++)
#pragma unroll
                for (int e = 0; e < 4; e++) {
                    int col = kv0 + nt * 8 + cb + (e & 1);
                    int row = rg0 + ((e >> 1) << 3);
                    if (col > row) scur[nt][e] = -1e30f;
                }
        }

        // ---- online softmax (base 2) ----
        float mx0 = -1e30f, mx1 = -1e30f;
#pragma unroll
        for (int nt = 0; nt < 8; nt++) {
            mx0 = fmaxf(mx0, fmaxf(scur[nt][0], scur[nt][1]));
            mx1 = fmaxf(mx1, fmaxf(scur[nt][2], scur[nt][3]));
        }
        mx0 = fmaxf(mx0, __shfl_xor_sync(0xffffffffu, mx0, 1));
        mx0 = fmaxf(mx0, __shfl_xor_sync(0xffffffffu, mx0, 2));
        mx1 = fmaxf(mx1, __shfl_xor_sync(0xffffffffu, mx1, 1));
        mx1 = fmaxf(mx1, __shfl_xor_sync(0xffffffffu, mx1, 2));

        float mn0 = fmaxf(mrow[0], mx0);
        float mn1 = fmaxf(mrow[1], mx1);
        bool nochange = (mn0 == mrow[0]) & (mn1 == mrow[1]);

        float sum0 = 0.0f, sum1 = 0.0f;
#pragma unroll
        for (int nt = 0; nt < 8; nt++) {
            scur[nt][0] = exp2f(scur[nt][0] - mn0);
            scur[nt][1] = exp2f(scur[nt][1] - mn0);
            scur[nt][2] = exp2f(scur[nt][2] - mn1);
            scur[nt][3] = exp2f(scur[nt][3] - mn1);
            sum0 += scur[nt][0] + scur[nt][1];
            sum1 += scur[nt][2] + scur[nt][3];
        }
        sum0 += __shfl_xor_sync(0xffffffffu, sum0, 1);
        sum0 += __shfl_xor_sync(0xffffffffu, sum0, 2);
        sum1 += __shfl_xor_sync(0xffffffffu, sum1, 1);
        sum1 += __shfl_xor_sync(0xffffffffu, sum1, 2);

        if (__all_sync(0xffffffffu, nochange)) {
            lsum[0] += sum0;
            lsum[1] += sum1;
        } else {
            float a0 = exp2f(mrow[0] - mn0);
            float a1 = exp2f(mrow[1] - mn1);
            lsum[0] = lsum[0] * a0 + sum0;
            lsum[1] = lsum[1] * a1 + sum1;
            mrow[0] = mn0;
            mrow[1] = mn1;
#pragma unroll
            for (int nt = 0; nt < 16; nt++) {
                oacc[nt][0] *= a0; oacc[nt][1] *= a0;
                oacc[nt][2] *= a1; oacc[nt][3] *= a1;
            }
        }

        // ---- O += P V  (V in slot j%3, natural via trans) ----
        const uint32_t vbase = sbase + QB + (j % 3) * STAGE + KVB;
#pragma unroll
        for (int kc2 = 0; kc2 < 4; kc2++) {
            uint32_t ph[4];
            ph[0] = pack_f16(scur[2 * kc2][0],     scur[2 * kc2][1]);
            ph[1] = pack_f16(scur[2 * kc2][2],     scur[2 * kc2][3]);
            ph[2] = pack_f16(scur[2 * kc2 + 1][0], scur[2 * kc2 + 1][1]);
            ph[3] = pack_f16(scur[2 * kc2 + 1][2], scur[2 * kc2 + 1][3]);
            int krow = kc2 * 16 + lrow;
#pragma unroll
            for (int g = 0; g < 8; g++) {
                int c = g * 2 + lsel;
                uint32_t off = (uint32_t)(krow * 256 + ((c ^ (krow & 7)) << 4));
                uint32_t vt[4];
                LDSM_X4_TRANS(vt[0], vt[1], vt[2], vt[3], vbase + off);
#pragma unroll
                for (int o = 0; o < 2; o++) {
                    int nt = g * 2 + o;
                    MMA_FP16(oacc[nt], ph, vt[2 * o], vt[2 * o + 1]);
                }
            }
        }

        if (have_next) {
#pragma unroll
            for (int nt = 0; nt < 8; nt++)
#pragma unroll
                for (int e = 0; e < 4; e++) scur[nt][e] = snext[nt][e];
        }
    }

    // ---- epilogue: normalize, emit fp16 O ----
    float inv0 = 1.0f / lsum[0];
    float inv1 = 1.0f / lsum[1];
    const long long r0 = (long long)rg0 * HID + h * HD;
    const long long r1 = r0 + 8LL * HID;
#pragma unroll
    for (int nt = 0; nt < 16; nt++) {
        int col = nt * 8 + cb;
        *reinterpret_cast<uint32_t*>(o16 + r0 + col) =
            pack_f16(oacc[nt][0] * inv0, oacc[nt][1] * inv0);
        *reinterpret_cast<uint32_t*>(o16 + r1 + col) =
            pack_f16(oacc[nt][2] * inv1, oacc[nt][3] * inv1);
    }
}

// ---------------------------------------------------------------------------
// Fused convert: X, Wq, Wk, Wv, Wo (fp32, natural layouts) -> fp16.
// ---------------------------------------------------------------------------
__global__ __launch_bounds__(256) void convert_all_kernel(
    const float* __restrict__ X,
    const float* __restrict__ Wq, const float* __restrict__ Wk,
    const float* __restrict__ Wv, const float* __restrict__ Wo,
    half* __restrict__ x16, half* __restrict__ wqkv16,
    half* __restrict__ wo16)
{
    const int B0 = 1048576;        // X:  4M elems / 4
    const int B1 = B0 + 1048576;   // Wq: 4M / 4
    const int B2 = B1 + 262144;    // Wk: 1M / 4
    const int B3 = B2 + 262144;    // Wv: 1M / 4
    const int B4 = B3 + 1048576;   // Wo: 4M / 4

    int idx = blockIdx.x * 256 + threadIdx.x;
    if (idx >= B4) return;

    const float* src;
    half* dst;
    long long off;
    if (idx < B0) {
        src = X + (long long)idx * 4;
        dst = x16; off = (long long)idx * 4;
    } else if (idx < B1) {
        int i = idx - B0;
        int k = i >> 9, n = (i & 511) * 4;
        src = Wq + (long long)i * 4;
        dst = wqkv16; off = (long long)k * NQKV + n;
    } else if (idx < B2) {
        int i = idx - B1;
        int k = i >> 7, n = (i & 127) * 4;
        src = Wk + (long long)i * 4;
        dst = wqkv16; off = (long long)k * NQKV + 2048 + n;
    } else if (idx < B3) {
        int i = idx - B2;
        int k = i >> 7, n = (i & 127) * 4;
        src = Wv + (long long)i * 4;
        dst = wqkv16; off = (long long)k * NQKV + 2560 + n;
    } else {
        int i = idx - B3;
        src = Wo + (long long)i * 4;
        dst = wo16; off = (long long)i * 4;
    }

    float4 v = *reinterpret_cast<const float4*>(src);
    *reinterpret_cast<half2*>(dst + off)     = __floats2half2_rn(v.x, v.y);
    *reinterpret_cast<half2*>(dst + off + 2) = __floats2half2_rn(v.z, v.w);
}

// ---------------------------------------------------------------------------
// Per-head RMSNorm + RoPE (Q/K) + plain V convert, 4 rows/block.
// Q pre-scaled by log2(e)/sqrt(HD): scores land in log2 domain for exp2f.
// ---------------------------------------------------------------------------
__global__ __launch_bounds__(512) void norm_rope_kernel(
    const float* __restrict__ qkv,
    const float* __restrict__ cosT, const float* __restrict__ sinT,
    const float* __restrict__ qscale, const float* __restrict__ kscale,
    half* __restrict__ q16, half* __restrict__ k16, half* __restrict__ v16)
{
    const float SCALE = 0.08838834764831845f * 1.4426950408889634f;
    int s = blockIdx.x * 4 + threadIdx.y;
    int h = blockIdx.y;
    int d = threadIdx.x;
    int ty = threadIdx.y;

    if (h >= NH + NKV) {  // V: pure fp16 convert, no norm
        int kv = h - NH - NKV;
        float x = qkv[(long long)s * NQKV + HID + NKV * HD + kv * HD + d];
        v16[((long long)kv * S + s) * HD + d] = __float2half_rn(x);
        return;
    }

    const float* src;
    long long dsto;
    const float* sc;
    half* dst;
    bool isQ = (h < NH);
    if (isQ) {
        src  = qkv + (long long)s * NQKV + h * HD;
        dsto = ((long long)h * S + s) * HD;
        sc = qscale; dst = q16;
    } else {
        int hk = h - NH;
        src  = qkv + (long long)s * NQKV + HID + hk * HD;
        dsto = ((long long)hk * S + s) * HD;
        sc = kscale; dst = k16;
    }

    float x = src[d];
    float v = x * x;
#pragma unroll
    for (int o = 16; o > 0; o >>= 1) v += __shfl_xor_sync(0xffffffffu, v, o);
    __shared__ float red[4][4];
    if ((d & 31) == 0) red[ty][d >> 5] = v;
    __syncthreads();
    float tot = red[ty][0] + red[ty][1] + red[ty][2] + red[ty][3];
    float r = rsqrtf(tot * (1.0f / HD) + EPS);

    __shared__ float xn[4][HD];
    float xv = x * r * sc[d];
    xn[ty][d] = xv;
    __syncthreads();
    float other = (d < HD / 2) ? -xn[ty][d + HD / 2] : xn[ty][d - HD / 2];

    float c  = cosT[(long long)s * HD + d];
    float sn = sinT[(long long)s * HD + d];
    float outv = xv * c + other * sn;
    if (isQ) outv *= SCALE;
    dst[dsto + d] = __float2half_rn(outv);
}

// ---------------------------------------------------------------------------
// Final RMSNorm over HID.
// ---------------------------------------------------------------------------
__global__ __launch_bounds__(256) void final_norm_kernel(
    const float* __restrict__ in, const float* __restrict__ scale,
    float* __restrict__ out)
{
    int s = blockIdx.x;
    int t = threadIdx.x;
    const float* row = in + (long long)s * HID;

    float loc[8];
    float ss = 0.0f;
#pragma unroll
    for (int c = 0; c < 8; c++) {
        float v = row[t + c * 256];
        loc[c] = v;
        ss += v * v;
    }
    __shared__ float red[8];
#pragma unroll
    for (int o = 16; o > 0; o >>= 1) ss += __shfl_xor_sync(0xffffffffu, ss, o);
    if ((t & 31) == 0) red[t >> 5] = ss;
    __syncthreads();
    if (t == 0) {
        float v = 0.0f;
        for (int w = 0; w < 8; w++) v += red[w];
        red[0] = v;
    }
    __syncthreads();
    float r = rsqrtf(red[0] * (1.0f / HID) + EPS);
#pragma unroll
    for (int c = 0; c < 8; c++)
        out[(long long)s * HID + t + c * 256] = loc[c] * r * scale[t + c * 256];
}

// ---------------------------------------------------------------------------
// Host launch
// ---------------------------------------------------------------------------
extern "C" void kernel_launch(void* const* d_in, const int* in_sizes, int n_in,
                              void* d_out, int out_size)
{
    const float* X    = (const float*)d_in[0];
    const float* cosT = (const float*)d_in[1];
    const float* sinT = (const float*)d_in[2];
    const float* Wq   = (const float*)d_in[3];
    const float* Wk   = (const float*)d_in[4];
    const float* Wv   = (const float*)d_in[5];
    const float* Wo   = (const float*)d_in[6];
    const float* qsc  = (const float*)d_in[7];
    const float* ksc  = (const float*)d_in[8];
    const float* lsc  = (const float*)d_in[9];
    float* out = (float*)d_out;

    float *qkv, *proj;
    half *x16, *wqkv16, *wo16, *q16, *k16, *v16, *o16;
    cudaGetSymbolAddress((void**)&qkv,    g_qkv);
    cudaGetSymbolAddress((void**)&proj,   g_proj);
    cudaGetSymbolAddress((void**)&x16,    g_x16);
    cudaGetSymbolAddress((void**)&wqkv16, g_wqkv16);
    cudaGetSymbolAddress((void**)&wo16,   g_wo16);
    cudaGetSymbolAddress((void**)&q16,    g_q16);
    cudaGetSymbolAddress((void**)&k16,    g_k16);
    cudaGetSymbolAddress((void**)&v16,    g_v16);
    cudaGetSymbolAddress((void**)&o16,    g_o16);

    const int SMEM_GEMM  = 3 * (128 * 64 * 2 + 64 * 64 * 2);       // 73728
    const int SMEM_FLASH = 64 * 128 * 2 + 3 * 2 * 64 * 128 * 2;    // 114688
    cudaFuncSetAttribute(mma_gemm_f16,
                         cudaFuncAttributeMaxDynamicSharedMemorySize, SMEM_GEMM);
    cudaFuncSetAttribute(flash_kernel,
                         cudaFuncAttributeMaxDynamicSharedMemorySize, SMEM_FLASH);

    // 1. Fused convert (X + all weights) -> fp16, natural layouts
    convert_all_kernel<<<(3670016 + 255) / 256, 256>>>(
        X, Wq, Wk, Wv, Wo, x16, wqkv16, wo16);

    // 2. Fused QKV projection (B natural via ldmatrix.trans)
    mma_gemm_f16<<<dim3(NQKV / 64, S / 128), 256, SMEM_GEMM>>>(
        S, NQKV, HID, x16, HID, wqkv16, NQKV, qkv, NQKV);

    // 3. Per-head RMSNorm + RoPE (Q pre-scaled, log2 domain) + V convert
    norm_rope_kernel<<<dim3(S / 4, NH + 2 * NKV), dim3(128, 4)>>>(
        qkv, cosT, sinT, qsc, ksc, q16, k16, v16);

    // 4. Fused flash attention (software-pipelined S) -> O fp16
    flash_kernel<<<dim3(S / 64, NH), 128, SMEM_FLASH>>>(q16, k16, v16, o16);

    // 5. Output projection
    mma_gemm_f16<<<dim3(HID / 64, S / 128), 256, SMEM_GEMM>>>(
        S, HID, HID, o16, HID, wo16, HID, proj, HID);

    // 6. Final RMSNorm
    final_norm_kernel<<<S, 256>>>(proj, lsc, out);
}

// round 17
// speedup vs baseline: 1.0373x; 1.0373x over previous
#include <cuda_runtime.h>
#include <cuda_fp16.h>
#include <math.h>
#include <stdint.h>

// Problem constants
#define S 2048
#define HID 2048
#define NH 16
#define NKV 4
#define HD 128
#define GRP (NH / NKV)
#define EPS 1e-6f
#define NQKV 3072  // NH*HD + 2*NKV*HD

// ---------------------------------------------------------------------------
// Scratch (device globals; allocation is forbidden)
// ---------------------------------------------------------------------------
__device__ float g_qkv[S * NQKV];          // fused QKV proj out (fp32)
__device__ half  g_x16[S * HID];           // X fp16 (natural [S][HID])
__device__ half  g_wqkv16[HID * NQKV];     // fused W fp16, natural [K][N]
__device__ half  g_wo16[HID * HID];        // Wo fp16, natural [K][N]
__device__ half  g_q16[NH * S * HD];       // Q fp16 (pre-scaled, log2 domain)
__device__ half  g_k16[NKV * S * HD];      // K fp16 [kv][s][d]
__device__ half  g_v16[NKV * S * HD];      // V fp16 [kv][s][d]
__device__ half  g_o16[S * HID];           // attention out fp16
__device__ float g_proj[S * HID];          // pre-final-norm

// ---------------------------------------------------------------------------
// PTX helpers (sm_80+ PTX only — legal under compute_103)
// ---------------------------------------------------------------------------
__device__ __forceinline__ uint32_t smem_u32(const void* p) {
    uint32_t a;
    asm("{ .reg .u64 t; cvta.to.shared.u64 t, %1; cvt.u32.u64 %0, t; }"
        : "=r"(a) : "l"(p));
    return a;
}

#define CP_ASYNC16(dst, src) \
    asm volatile("cp.async.cg.shared.global [%0], [%1], 16;" \
        :: "r"(dst), "l"(src))
#define CP_COMMIT() asm volatile("cp.async.commit_group;" ::: "memory")
#define CP_WAIT0() asm volatile("cp.async.wait_group 0;" ::: "memory")
#define CP_WAIT1() asm volatile("cp.async.wait_group 1;" ::: "memory")
#define CP_WAIT2() asm volatile("cp.async.wait_group 2;" ::: "memory")
#define CP_WAIT3() asm volatile("cp.async.wait_group 3;" ::: "memory")

#define LDSM_X4(r0, r1, r2, r3, addr) \
    asm volatile("ldmatrix.sync.aligned.m8n8.x4.shared.b16 {%0,%1,%2,%3}, [%4];" \
        : "=r"(r0), "=r"(r1), "=r"(r2), "=r"(r3) : "r"(addr))

#define LDSM_X4_TRANS(r0, r1, r2, r3, addr) \
    asm volatile("ldmatrix.sync.aligned.m8n8.x4.trans.shared.b16 {%0,%1,%2,%3}, [%4];" \
        : "=r"(r0), "=r"(r1), "=r"(r2), "=r"(r3) : "r"(addr))

#define MMA_FP16(d, a, b0, b1) \
    asm volatile("mma.sync.aligned.m16n8k16.row.col.f32.f16.f16.f32 " \
        "{%0,%1,%2,%3}, {%4,%5,%6,%7}, {%8,%9}, {%0,%1,%2,%3};" \
        : "+f"((d)[0]), "+f"((d)[1]), "+f"((d)[2]), "+f"((d)[3]) \
        : "r"((a)[0]), "r"((a)[1]), "r"((a)[2]), "r"((a)[3]), \
          "r"(b0), "r"(b1))

__device__ __forceinline__ uint32_t pack_f16(float v0, float v1) {
    half h0 = __float2half_rn(v0);
    half h1 = __float2half_rn(v1);
    return (uint32_t)__half_as_ushort(h0) |
           ((uint32_t)__half_as_ushort(h1) << 16);
}

// ---------------------------------------------------------------------------
// fp16 GEMM: C[M,N] = A16[M,K] @ B16[K,N]  (B natural row-major; fragments
// built with ldmatrix.trans). CTA tile 128x64, warp 32x32, BK=64, 4-stage
// cp.async ring, 24 KB/stage -> 96 KB smem, 2 CTAs/SM.
// ---------------------------------------------------------------------------
__global__ __launch_bounds__(256, 2) void mma_gemm_f16(
    int M, int N, int K,
    const half* __restrict__ A16, int lda,
    const half* __restrict__ B16, int ldb,
    float* __restrict__ C, int ldc)
{
    constexpr int BM = 128, BN = 64, BK = 64;
    constexpr int ASUB = BM * BK * 2;      // 16 KB
    constexpr int BSUB = BK * BN * 2;      // 8 KB
    constexpr int STAGE = ASUB + BSUB;     // 24 KB

    const int m0 = blockIdx.y * BM;
    const int n0 = blockIdx.x * BN;
    const int nIter = K / BK;

    extern __shared__ char smem[];
    const uint32_t sbase = smem_u32(smem);

    const int tid  = threadIdx.x;
    const int wid  = tid >> 5;
    const int lane = tid & 31;
    const int wm   = wid >> 1;
    const int wn   = wid & 1;

    auto load_stage = [&](int st, int k0) {
        const uint32_t base = sbase + st * STAGE;
#pragma unroll
        for (int t = 0; t < 4; t++) {
            int idx = tid + t * 256;          // A: 128 rows x 8 chunks
            int r = idx >> 3;
            int c = idx & 7;
            uint32_t soff = (uint32_t)(r * 128 + ((c ^ (r & 7)) << 4));
            long long ga = (long long)(m0 + r) * lda + k0 + c * 8;
            CP_ASYNC16(base + soff, (const char*)(A16 + ga));
        }
#pragma unroll
        for (int t = 0; t < 2; t++) {
            int idx = tid + t * 256;          // B: 64 k-rows x 8 n-chunks
            int r = idx >> 3;
            int c = idx & 7;
            uint32_t soff = (uint32_t)(r * 128 + ((c ^ (r & 7)) << 4));
            long long gb = (long long)(k0 + r) * ldb + n0 + c * 8;
            CP_ASYNC16(base + ASUB + soff, (const char*)(B16 + gb));
        }
        CP_COMMIT();
    };

    const int lrow = lane & 15;
    const int lsel = lane >> 4;
    int arow[2];
#pragma unroll
    for (int mt = 0; mt < 2; mt++) arow[mt] = wm * 32 + mt * 16 + lrow;

    float acc[2][4][4];
#pragma unroll
    for (int mt = 0; mt < 2; mt++)
#pragma unroll
        for (int j = 0; j < 4; j++)
#pragma unroll
            for (int e = 0; e < 4; e++) acc[mt][j][e] = 0.0f;

    load_stage(0, 0);
    if (nIter > 1) load_stage(1, BK);
    if (nIter > 2) load_stage(2, 2 * BK);

    for (int it = 0; it < nIter; it++) {
        if (it + 3 < nIter) { load_stage((it + 3) & 3, (it + 3) * BK); CP_WAIT3(); }
        else if (it + 2 < nIter) { CP_WAIT2(); }
        else if (it + 1 < nIter) { CP_WAIT1(); }
        else { CP_WAIT0(); }
        __syncthreads();

        const uint32_t base = sbase + (it & 3) * STAGE;
#pragma unroll
        for (int ks = 0; ks < 4; ks++) {
            const int achunk = ks * 2 + lsel;
            uint32_t ah[2][4], bt[2][4];
#pragma unroll
            for (int mt = 0; mt < 2; mt++) {
                uint32_t off = (uint32_t)(arow[mt] * 128 +
                               ((achunk ^ (arow[mt] & 7)) << 4));
                LDSM_X4(ah[mt][0], ah[mt][1], ah[mt][2], ah[mt][3], base + off);
            }
            int krow = ks * 16 + lrow;
#pragma unroll
            for (int g = 0; g < 2; g++) {
                int c = wn * 4 + g * 2 + lsel;
                uint32_t off = (uint32_t)(krow * 128 + ((c ^ (krow & 7)) << 4));
                LDSM_X4_TRANS(bt[g][0], bt[g][1], bt[g][2], bt[g][3],
                              base + ASUB + off);
            }
#pragma unroll
            for (int mt = 0; mt < 2; mt++)
#pragma unroll
                for (int j = 0; j < 4; j++) {
                    int g = j >> 1, o = j & 1;
                    MMA_FP16(acc[mt][j], ah[mt], bt[g][2 * o], bt[g][2 * o + 1]);
                }
        }
        __syncthreads();
    }

    const int er = lane >> 2;
    const int ec = (lane & 3) * 2;
#pragma unroll
    for (int mt = 0; mt < 2; mt++) {
        int r0 = m0 + wm * 32 + mt * 16 + er;
#pragma unroll
        for (int j = 0; j < 4; j++) {
            int col = n0 + wn * 32 + j * 8 + ec;
            *reinterpret_cast<float2*>(C + (long long)r0 * ldc + col) =
                make_float2(acc[mt][j][0], acc[mt][j][1]);
            *reinterpret_cast<float2*>(C + (long long)(r0 + 8) * ldc + col) =
                make_float2(acc[mt][j][2], acc[mt][j][3]);
        }
    }
}

// ---------------------------------------------------------------------------
// Fused flash attention: BQ=64 rows, 4 warps x 16 rows, 128 threads,
// 2 CTAs/SM, 3-stage KV pipeline (one barrier/iter; prefetch after barrier).
// Scores in log2 domain (Q pre-scaled by log2e/sqrt(d)) -> exp2f.
// oacc rescale skipped when the running max is unchanged across the warp.
// (R14/R15 structure — R16's register-heavy S-pipelining reverted.)
// ---------------------------------------------------------------------------
__global__ __launch_bounds__(128, 2) void flash_kernel(
    const half* __restrict__ q16, const half* __restrict__ k16,
    const half* __restrict__ v16, half* __restrict__ o16)
{
    constexpr int BQ = 64, BKV = 64;
    constexpr int QB = BQ * HD * 2;            // 16 KB
    constexpr int KVB = BKV * HD * 2;          // 16 KB each
    constexpr int STAGE = 2 * KVB;             // 32 KB (K + V)

    const int h   = blockIdx.y;
    const int qt  = gridDim.x - 1 - blockIdx.x;  // largest m0 first
    const int m0  = qt * BQ;
    const int kvh = h / GRP;
    const int jn  = qt + 1;

    const half* q_h = q16 + (long long)h * S * HD;
    const half* k_h = k16 + (long long)kvh * S * HD;
    const half* v_h = v16 + (long long)kvh * S * HD;

    extern __shared__ char smem[];
    const uint32_t sbase = smem_u32(smem);

    const int tid  = threadIdx.x;
    const int w    = tid >> 5;
    const int lane = tid & 31;
    const int lrow = lane & 15;
    const int lsel = lane >> 4;

    auto load_q = [&]() {
#pragma unroll
        for (int t = 0; t < 8; t++) {
            int idx = tid + t * 128;            // [0, 1024): 64 rows x 16 c
            int r = idx >> 4, c = idx & 15;
            uint32_t soff = (uint32_t)(r * 256 + ((c ^ (r & 7)) << 4));
            long long g = (long long)(m0 + r) * HD + c * 8;
            CP_ASYNC16(sbase + soff, (const char*)(q_h + g));
        }
    };
    auto load_stage = [&](int st, int kv0) {
        const uint32_t base = sbase + QB + st * STAGE;
#pragma unroll
        for (int t = 0; t < 8; t++) {           // K: 64 rows x 16 chunks
            int idx = tid + t * 128;
            int r = idx >> 4, c = idx & 15;
            uint32_t soff = (uint32_t)(r * 256 + ((c ^ (r & 7)) << 4));
            long long g = (long long)(kv0 + r) * HD + c * 8;
            CP_ASYNC16(base + soff, (const char*)(k_h + g));
        }
#pragma unroll
        for (int t = 0; t < 8; t++) {           // V: 64 rows x 16 chunks
            int idx = tid + t * 128;
            int r = idx >> 4, c = idx & 15;
            uint32_t soff = (uint32_t)(r * 256 + ((c ^ (r & 7)) << 4));
            long long g = (long long)(kv0 + r) * HD + c * 8;
            CP_ASYNC16(base + KVB + soff, (const char*)(v_h + g));
        }
        CP_COMMIT();
    };

    load_q();
    load_stage(0, 0);
    CP_COMMIT();                     // group 0 = Q + stage0
    if (jn > 1) load_stage(1, BKV);  // group 1 = stage1

    uint32_t qh[8][4];
    float oacc[16][4];
#pragma unroll
    for (int nt = 0; nt < 16; nt++)
#pragma unroll
        for (int e = 0; e < 4; e++) oacc[nt][e] = 0.0f;
    float mrow[2] = {-1e30f, -1e30f};
    float lsum[2] = {0.0f, 0.0f};

    const int rg0 = m0 + w * 16 + (lane >> 2);
    const int cb  = (lane & 3) * 2;

    for (int j = 0; j < jn; j++) {
        const int kv0 = j * BKV;
        const bool masked = (kv0 + BKV > m0);   // only the diagonal tile

        if (j + 1 < jn) CP_WAIT1(); else CP_WAIT0();
        __syncthreads();
        if (j + 2 < jn) load_stage((j + 2) % 3, (j + 2) * BKV);

        if (j == 0) {
            int row = w * 16 + lrow;
#pragma unroll
            for (int kchunk = 0; kchunk < 8; kchunk++) {
                int c = kchunk * 2 + lsel;
                uint32_t off = (uint32_t)(row * 256 + ((c ^ (row & 7)) << 4));
                LDSM_X4(qh[kchunk][0], qh[kchunk][1], qh[kchunk][2],
                        qh[kchunk][3], sbase + off);
            }
        }

        const uint32_t base = sbase + QB + (j % 3) * STAGE;

        // ---- S = Q K^T  (log2 domain) ----
        float s[8][4];
#pragma unroll
        for (int nt = 0; nt < 8; nt++)
#pragma unroll
            for (int e = 0; e < 4; e++) s[nt][e] = 0.0f;

#pragma unroll
        for (int kchunk = 0; kchunk < 8; kchunk++) {
            int c = kchunk * 2 + lsel;
#pragma unroll
            for (int g = 0; g < 4; g++) {
                int row = g * 16 + lrow;
                uint32_t off = (uint32_t)(row * 256 + ((c ^ (row & 7)) << 4));
                uint32_t bh[4];
                LDSM_X4(bh[0], bh[1], bh[2], bh[3], base + off);
#pragma unroll
                for (int o = 0; o < 2; o++) {
                    int nt = g * 2 + o;
                    MMA_FP16(s[nt], qh[kchunk], bh[o], bh[2 + o]);
                }
            }
        }

        // ---- causal mask (diagonal tile only) ----
        if (masked) {
#pragma unroll
            for (int nt = 0; nt < 8; nt++)
#pragma unroll
                for (int e = 0; e < 4; e++) {
                    int col = kv0 + nt * 8 + cb + (e & 1);
                    int row = rg0 + ((e >> 1) << 3);
                    if (col > row) s[nt][e] = -1e30f;
                }
        }

        // ---- online softmax (base 2) ----
        float mx0 = -1e30f, mx1 = -1e30f;
#pragma unroll
        for (int nt = 0; nt < 8; nt++) {
            mx0 = fmaxf(mx0, fmaxf(s[nt][0], s[nt][1]));
            mx1 = fmaxf(mx1, fmaxf(s[nt][2], s[nt][3]));
        }
        mx0 = fmaxf(mx0, __shfl_xor_sync(0xffffffffu, mx0, 1));
        mx0 = fmaxf(mx0, __shfl_xor_sync(0xffffffffu, mx0, 2));
        mx1 = fmaxf(mx1, __shfl_xor_sync(0xffffffffu, mx1, 1));
        mx1 = fmaxf(mx1, __shfl_xor_sync(0xffffffffu, mx1, 2));

        float mn0 = fmaxf(mrow[0], mx0);
        float mn1 = fmaxf(mrow[1], mx1);
        bool nochange = (mn0 == mrow[0]) & (mn1 == mrow[1]);

        float sum0 = 0.0f, sum1 = 0.0f;
#pragma unroll
        for (int nt = 0; nt < 8; nt++) {
            s[nt][0] = exp2f(s[nt][0] - mn0);
            s[nt][1] = exp2f(s[nt][1] - mn0);
            s[nt][2] = exp2f(s[nt][2] - mn1);
            s[nt][3] = exp2f(s[nt][3] - mn1);
            sum0 += s[nt][0] + s[nt][1];
            sum1 += s[nt][2] + s[nt][3];
        }
        sum0 += __shfl_xor_sync(0xffffffffu, sum0, 1);
        sum0 += __shfl_xor_sync(0xffffffffu, sum0, 2);
        sum1 += __shfl_xor_sync(0xffffffffu, sum1, 1);
        sum1 += __shfl_xor_sync(0xffffffffu, sum1, 2);

        if (__all_sync(0xffffffffu, nochange)) {
            lsum[0] += sum0;
            lsum[1] += sum1;
        } else {
            float a0 = exp2f(mrow[0] - mn0);
            float a1 = exp2f(mrow[1] - mn1);
            lsum[0] = lsum[0] * a0 + sum0;
            lsum[1] = lsum[1] * a1 + sum1;
            mrow[0] = mn0;
            mrow[1] = mn1;
#pragma unroll
            for (int nt = 0; nt < 16; nt++) {
                oacc[nt][0] *= a0; oacc[nt][1] *= a0;
                oacc[nt][2] *= a1; oacc[nt][3] *= a1;
            }
        }

        // ---- O += P V  (V natural via trans: k-rows = s, n = d) ----
#pragma unroll
        for (int kc2 = 0; kc2 < 4; kc2++) {
            uint32_t ph[4];
            ph[0] = pack_f16(s[2 * kc2][0],     s[2 * kc2][1]);
            ph[1] = pack_f16(s[2 * kc2][2],     s[2 * kc2][3]);
            ph[2] = pack_f16(s[2 * kc2 + 1][0], s[2 * kc2 + 1][1]);
            ph[3] = pack_f16(s[2 * kc2 + 1][2], s[2 * kc2 + 1][3]);
            int krow = kc2 * 16 + lrow;
#pragma unroll
            for (int g = 0; g < 8; g++) {
                int c = g * 2 + lsel;
                uint32_t off = (uint32_t)(KVB + krow * 256 +
                                          ((c ^ (krow & 7)) << 4));
                uint32_t vt[4];
                LDSM_X4_TRANS(vt[0], vt[1], vt[2], vt[3], base + off);
#pragma unroll
                for (int o = 0; o < 2; o++) {
                    int nt = g * 2 + o;
                    MMA_FP16(oacc[nt], ph, vt[2 * o], vt[2 * o + 1]);
                }
            }
        }
    }

    // ---- epilogue: normalize, emit fp16 O ----
    float inv0 = 1.0f / lsum[0];
    float inv1 = 1.0f / lsum[1];
    const long long r0 = (long long)rg0 * HID + h * HD;
    const long long r1 = r0 + 8LL * HID;
#pragma unroll
    for (int nt = 0; nt < 16; nt++) {
        int col = nt * 8 + cb;
        *reinterpret_cast<uint32_t*>(o16 + r0 + col) =
            pack_f16(oacc[nt][0] * inv0, oacc[nt][1] * inv0);
        *reinterpret_cast<uint32_t*>(o16 + r1 + col) =
            pack_f16(oacc[nt][2] * inv1, oacc[nt][3] * inv1);
    }
}

// ---------------------------------------------------------------------------
// Fused convert: X, Wq, Wk, Wv, Wo (fp32, natural layouts) -> fp16.
// ---------------------------------------------------------------------------
__global__ __launch_bounds__(256) void convert_all_kernel(
    const float* __restrict__ X,
    const float* __restrict__ Wq, const float* __restrict__ Wk,
    const float* __restrict__ Wv, const float* __restrict__ Wo,
    half* __restrict__ x16, half* __restrict__ wqkv16,
    half* __restrict__ wo16)
{
    const int B0 = 1048576;        // X:  4M elems / 4
    const int B1 = B0 + 1048576;   // Wq: 4M / 4
    const int B2 = B1 + 262144;    // Wk: 1M / 4
    const int B3 = B2 + 262144;    // Wv: 1M / 4
    const int B4 = B3 + 1048576;   // Wo: 4M / 4

    int idx = blockIdx.x * 256 + threadIdx.x;
    if (idx >= B4) return;

    const float* src;
    half* dst;
    long long off;
    if (idx < B0) {
        src = X + (long long)idx * 4;
        dst = x16; off = (long long)idx * 4;
    } else if (idx < B1) {
        int i = idx - B0;
        int k = i >> 9, n = (i & 511) * 4;
        src = Wq + (long long)i * 4;
        dst = wqkv16; off = (long long)k * NQKV + n;
    } else if (idx < B2) {
        int i = idx - B1;
        int k = i >> 7, n = (i & 127) * 4;
        src = Wk + (long long)i * 4;
        dst = wqkv16; off = (long long)k * NQKV + 2048 + n;
    } else if (idx < B3) {
        int i = idx - B2;
        int k = i >> 7, n = (i & 127) * 4;
        src = Wv + (long long)i * 4;
        dst = wqkv16; off = (long long)k * NQKV + 2560 + n;
    } else {
        int i = idx - B3;
        src = Wo + (long long)i * 4;
        dst = wo16; off = (long long)i * 4;
    }

    float4 v = *reinterpret_cast<const float4*>(src);
    *reinterpret_cast<half2*>(dst + off)     = __floats2half2_rn(v.x, v.y);
    *reinterpret_cast<half2*>(dst + off + 2) = __floats2half2_rn(v.z, v.w);
}

// ---------------------------------------------------------------------------
// Per-head RMSNorm + RoPE (Q/K) + plain V convert, 4 rows/block.
// Q pre-scaled by log2(e)/sqrt(HD): scores land in log2 domain for exp2f.
// ---------------------------------------------------------------------------
__global__ __launch_bounds__(512) void norm_rope_kernel(
    const float* __restrict__ qkv,
    const float* __restrict__ cosT, const float* __restrict__ sinT,
    const float* __restrict__ qscale, const float* __restrict__ kscale,
    half* __restrict__ q16, half* __restrict__ k16, half* __restrict__ v16)
{
    const float SCALE = 0.08838834764831845f * 1.4426950408889634f;
    int s = blockIdx.x * 4 + threadIdx.y;
    int h = blockIdx.y;
    int d = threadIdx.x;
    int ty = threadIdx.y;

    if (h >= NH + NKV) {  // V: pure fp16 convert, no norm
        int kv = h - NH - NKV;
        float x = qkv[(long long)s * NQKV + HID + NKV * HD + kv * HD + d];
        v16[((long long)kv * S + s) * HD + d] = __float2half_rn(x);
        return;
    }

    const float* src;
    long long dsto;
    const float* sc;
    half* dst;
    bool isQ = (h < NH);
    if (isQ) {
        src  = qkv + (long long)s * NQKV + h * HD;
        dsto = ((long long)h * S + s) * HD;
        sc = qscale; dst = q16;
    } else {
        int hk = h - NH;
        src  = qkv + (long long)s * NQKV + HID + hk * HD;
        dsto = ((long long)hk * S + s) * HD;
        sc = kscale; dst = k16;
    }

    float x = src[d];
    float v = x * x;
#pragma unroll
    for (int o = 16; o > 0; o >>= 1) v += __shfl_xor_sync(0xffffffffu, v, o);
    __shared__ float red[4][4];
    if ((d & 31) == 0) red[ty][d >> 5] = v;
    __syncthreads();
    float tot = red[ty][0] + red[ty][1] + red[ty][2] + red[ty][3];
    float r = rsqrtf(tot * (1.0f / HD) + EPS);

    __shared__ float xn[4][HD];
    float xv = x * r * sc[d];
    xn[ty][d] = xv;
    __syncthreads();
    float other = (d < HD / 2) ? -xn[ty][d + HD / 2] : xn[ty][d - HD / 2];

    float c  = cosT[(long long)s * HD + d];
    float sn = sinT[(long long)s * HD + d];
    float outv = xv * c + other * sn;
    if (isQ) outv *= SCALE;
    dst[dsto + d] = __float2half_rn(outv);
}

// ---------------------------------------------------------------------------
// Final RMSNorm over HID.
// ---------------------------------------------------------------------------
__global__ __launch_bounds__(256) void final_norm_kernel(
    const float* __restrict__ in, const float* __restrict__ scale,
    float* __restrict__ out)
{
    int s = blockIdx.x;
    int t = threadIdx.x;
    const float* row = in + (long long)s * HID;

    float loc[8];
    float ss = 0.0f;
#pragma unroll
    for (int c = 0; c < 8; c++) {
        float v = row[t + c * 256];
        loc[c] = v;
        ss += v * v;
    }
    __shared__ float red[8];
#pragma unroll
    for (int o = 16; o > 0; o >>= 1) ss += __shfl_xor_sync(0xffffffffu, ss, o);
    if ((t & 31) == 0) red[t >> 5] = ss;
    __syncthreads();
    if (t == 0) {
        float v = 0.0f;
        for (int w = 0; w < 8; w++) v += red[w];
        red[0] = v;
    }
    __syncthreads();
    float r = rsqrtf(red[0] * (1.0f / HID) + EPS);
#pragma unroll
    for (int c = 0; c < 8; c++)
        out[(long long)s * HID + t + c * 256] = loc[c] * r * scale[t + c * 256];
}

// ---------------------------------------------------------------------------
// Host launch
// ---------------------------------------------------------------------------
extern "C" void kernel_launch(void* const* d_in, const int* in_sizes, int n_in,
                              void* d_out, int out_size)
{
    const float* X    = (const float*)d_in[0];
    const float* cosT = (const float*)d_in[1];
    const float* sinT = (const float*)d_in[2];
    const float* Wq   = (const float*)d_in[3];
    const float* Wk   = (const float*)d_in[4];
    const float* Wv   = (const float*)d_in[5];
    const float* Wo   = (const float*)d_in[6];
    const float* qsc  = (const float*)d_in[7];
    const float* ksc  = (const float*)d_in[8];
    const float* lsc  = (const float*)d_in[9];
    float* out = (float*)d_out;

    float *qkv, *proj;
    half *x16, *wqkv16, *wo16, *q16, *k16, *v16, *o16;
    cudaGetSymbolAddress((void**)&qkv,    g_qkv);
    cudaGetSymbolAddress((void**)&proj,   g_proj);
    cudaGetSymbolAddress((void**)&x16,    g_x16);
    cudaGetSymbolAddress((void**)&wqkv16, g_wqkv16);
    cudaGetSymbolAddress((void**)&wo16,   g_wo16);
    cudaGetSymbolAddress((void**)&q16,    g_q16);
    cudaGetSymbolAddress((void**)&k16,    g_k16);
    cudaGetSymbolAddress((void**)&v16,    g_v16);
    cudaGetSymbolAddress((void**)&o16,    g_o16);

    const int SMEM_GEMM  = 4 * (128 * 64 * 2 + 64 * 64 * 2);       // 98304
    const int SMEM_FLASH = 64 * 128 * 2 + 3 * 2 * 64 * 128 * 2;    // 114688
    cudaFuncSetAttribute(mma_gemm_f16,
                         cudaFuncAttributeMaxDynamicSharedMemorySize, SMEM_GEMM);
    cudaFuncSetAttribute(flash_kernel,
                         cudaFuncAttributeMaxDynamicSharedMemorySize, SMEM_FLASH);

    // 1. Fused convert (X + all weights) -> fp16, natural layouts
    convert_all_kernel<<<(3670016 + 255) / 256, 256>>>(
        X, Wq, Wk, Wv, Wo, x16, wqkv16, wo16);

    // 2. Fused QKV projection (4-stage pipeline)
    mma_gemm_f16<<<dim3(NQKV / 64, S / 128), 256, SMEM_GEMM>>>(
        S, NQKV, HID, x16, HID, wqkv16, NQKV, qkv, NQKV);

    // 3. Per-head RMSNorm + RoPE (Q pre-scaled, log2 domain) + V convert
    norm_rope_kernel<<<dim3(S / 4, NH + 2 * NKV), dim3(128, 4)>>>(
        qkv, cosT, sinT, qsc, ksc, q16, k16, v16);

    // 4. Fused flash attention (R14/R15 structure) -> O fp16
    flash_kernel<<<dim3(S / 64, NH), 128, SMEM_FLASH>>>(q16, k16, v16, o16);

    // 5. Output projection (4-stage pipeline)
    mma_gemm_f16<<<dim3(HID / 64, S / 128), 256, SMEM_GEMM>>>(
        S, HID, HID, o16, HID, wo16, HID, proj, HID);

    // 6. Final RMSNorm
    final_norm_kernel<<<S, 256>>>(proj, lsc, out);
}